// round 17
// baseline (speedup 1.0000x reference)
#include <cuda_runtime.h>
#include <cuda_bf16.h>

// B=1, H=16, S=4096, D=64, fp32, NO softmax.
// (Q K^T) V == Q (K^T V);  K^T V is [64x64] per head -> 64x fewer FLOPs.
// R16: bf16x3 (m16n8k16) compensated GEMMs.
//  ktv: 4x 32-row pipelined phases, 36.9KB smem -> 4 CTA/SM, K/V staging split
//       across thread halves.
//  reduce_m: emits pre-packed bf16 hi/lo planes (M split once per head).
//  qm: 128-row blocks, M planes copied (no pack ALU), 55.3KB dynamic smem.
#define HEADS 16
#define SEQ   4096
#define DIM   64
#define NSPLIT 32
#define CHUNK (SEQ / NSPLIT)   // 128 rows per partial block

__device__ __align__(16) float    g_partial[HEADS * NSPLIT * DIM * DIM];  // 8 MB
__device__ __align__(16) unsigned g_Mhi[HEADS * 32 * DIM];                // k-pair words
__device__ __align__(16) unsigned g_Mlo[HEADS * 32 * DIM];

// ---- bf16 split/pack helpers ----------------------------------------------
__device__ __forceinline__ void split_bf16(float x, __nv_bfloat16& hi, __nv_bfloat16& lo) {
    hi = __float2bfloat16_rn(x);
    lo = __float2bfloat16_rn(x - __bfloat162float(hi));
}
__device__ __forceinline__ void pack2(float x0, float x1, unsigned& whi, unsigned& wlo) {
    __nv_bfloat16 h0, l0, h1, l1;
    split_bf16(x0, h0, l0);
    split_bf16(x1, h1, l1);
    __nv_bfloat162 ph = __halves2bfloat162(h0, h1);
    __nv_bfloat162 pl = __halves2bfloat162(l0, l1);
    whi = *(unsigned*)&ph;
    wlo = *(unsigned*)&pl;
}
__device__ __forceinline__ void mma_bf16(float* d, const unsigned* a, const unsigned* b) {
    asm("mma.sync.aligned.m16n8k16.row.col.f32.bf16.bf16.f32 "
        "{%0,%1,%2,%3}, {%4,%5,%6,%7}, {%8,%9}, {%0,%1,%2,%3};"
        : "+f"(d[0]), "+f"(d[1]), "+f"(d[2]), "+f"(d[3])
        : "r"(a[0]), "r"(a[1]), "r"(a[2]), "r"(a[3]), "r"(b[0]), "r"(b[1]));
}
__device__ __forceinline__ void mma_x3(float* acc, const unsigned* ah, const unsigned* al,
                                       const unsigned* bh, const unsigned* bl) {
    mma_bf16(acc, ah, bh);
    mma_bf16(acc, ah, bl);
    mma_bf16(acc, al, bh);
}

#define KSTR 72   // u32 row stride: ==8 mod 32 -> (8t+g) gathers conflict-free

// ---------------------------------------------------------------------------
// Kernel 1: partial M = K_chunk^T @ V_chunk.  grid = HEADS*NSPLIT, 512 thr.
// Planes [sp=s/2][d]: word = bf16(s=2sp) | bf16(s=2sp+1)<<16  (mma k-pair).
// 16 warps: (wid&3) -> d1 block of 16; (wid>>2) -> d2 block of 16 (nt=2).
// FOUR 32-row phases, ping-pong stages, register prefetch, 1 sync/phase.
// Staging: threads 0-255 stage K, 256-511 stage V (1 slot each).
// Dynamic smem: 2 stages * 4 planes * 16*KSTR u32 * 4B = 36.9 KB -> 4 CTA/SM.
// ---------------------------------------------------------------------------
#define KTV_THREADS 512
#define ROWS_PER_STAGE 32           // 16 s-pairs
#define PLANE_WORDS (16 * KSTR)
#define STAGE_WORDS (4 * PLANE_WORDS)
#define KTV_SMEM (2 * STAGE_WORDS * 4)
#define NPHASE (CHUNK / ROWS_PER_STAGE)   // 4

__global__ __launch_bounds__(KTV_THREADS) void ktv_partial(const float* __restrict__ Kp,
                                                           const float* __restrict__ Vp) {
    extern __shared__ __align__(16) unsigned sm[];   // [2][4][16][KSTR]

    const int h   = blockIdx.x / NSPLIT;
    const int spl = blockIdx.x % NSPLIT;
    const float* Kh = Kp + ((size_t)h * SEQ + (size_t)spl * CHUNK) * DIM;
    const float* Vh = Vp + ((size_t)h * SEQ + (size_t)spl * CHUNK) * DIM;

    const int tid  = threadIdx.x;
    const int wid  = tid >> 5;
    const int lane = tid & 31;
    const int g = lane >> 2;      // 0..7
    const int t = lane & 3;       // 0..3
    const int d1_0 = (wid & 3) * 16;
    const int d2_0 = (wid >> 2) * 16;

    // staging: half 0 -> K, half 1 -> V; slot s in [0,256)
    const int half = tid >> 8;
    const int slot = tid & 255;
    const int sp = slot >> 4;               // s-pair 0..15
    const int c4 = (slot & 15) << 2;        // col quad
    const float* Src = half ? Vh : Kh;

    float4 b0, b1;                          // rows 2sp, 2sp+1
    float acc[2][4] = {};

    auto fetch = [&](int t0) {
        b0 = *(const float4*)&Src[(size_t)(t0 + 2 * sp) * DIM + c4];
        b1 = *(const float4*)&Src[(size_t)(t0 + 2 * sp + 1) * DIM + c4];
    };
    auto stash = [&](int st) {
        unsigned* hiP = sm + st * STAGE_WORDS + half * 2 * PLANE_WORDS;
        unsigned* loP = hiP + PLANE_WORDS;
        uint4 whi, wlo;
        pack2(b0.x, b1.x, whi.x, wlo.x);
        pack2(b0.y, b1.y, whi.y, wlo.y);
        pack2(b0.z, b1.z, whi.z, wlo.z);
        pack2(b0.w, b1.w, whi.w, wlo.w);
        *(uint4*)&hiP[sp * KSTR + c4] = whi;
        *(uint4*)&loP[sp * KSTR + c4] = wlo;
    };

    fetch(0);
    stash(0);
    __syncthreads();

    #pragma unroll
    for (int ph = 0; ph < NPHASE; ph++) {
        if (ph < NPHASE - 1)
            fetch((ph + 1) * ROWS_PER_STAGE);            // overlap LDG with MMA

        const unsigned* Khi = sm + (ph & 1) * STAGE_WORDS;
        const unsigned* Klo = Khi + PLANE_WORDS;
        const unsigned* Vhi = Klo + PLANE_WORDS;
        const unsigned* Vlo = Vhi + PLANE_WORDS;

        #pragma unroll
        for (int ks = 0; ks < 2; ks++) {                 // two k16 slabs (16 sp rows)
            const int sb = ks * 8;
            unsigned ah[4], al[4];
            ah[0] = Khi[(sb + t) * KSTR + d1_0 + g];
            al[0] = Klo[(sb + t) * KSTR + d1_0 + g];
            ah[1] = Khi[(sb + t) * KSTR + d1_0 + g + 8];
            al[1] = Klo[(sb + t) * KSTR + d1_0 + g + 8];
            ah[2] = Khi[(sb + t + 4) * KSTR + d1_0 + g];
            al[2] = Klo[(sb + t + 4) * KSTR + d1_0 + g];
            ah[3] = Khi[(sb + t + 4) * KSTR + d1_0 + g + 8];
            al[3] = Klo[(sb + t + 4) * KSTR + d1_0 + g + 8];
            #pragma unroll
            for (int nt = 0; nt < 2; nt++) {
                const int col = d2_0 + nt * 8 + g;
                unsigned bh[2], bl[2];
                bh[0] = Vhi[(sb + t) * KSTR + col];
                bl[0] = Vlo[(sb + t) * KSTR + col];
                bh[1] = Vhi[(sb + t + 4) * KSTR + col];
                bl[1] = Vlo[(sb + t + 4) * KSTR + col];
                mma_x3(acc[nt], ah, al, bh, bl);
            }
        }

        if (ph < NPHASE - 1) {
            stash((ph + 1) & 1);   // other buffer (its readers finished pre-ph sync)
            __syncthreads();       // visible before next phase's MMA
        }
    }

    float* outp = g_partial + ((size_t)h * NSPLIT + spl) * DIM * DIM;
    #pragma unroll
    for (int nt = 0; nt < 2; nt++) {
        const int col = d2_0 + nt * 8 + 2 * t;
        const int row = d1_0 + g;
        *(float2*)&outp[row * DIM + col]       = make_float2(acc[nt][0], acc[nt][1]);
        *(float2*)&outp[(row + 8) * DIM + col] = make_float2(acc[nt][2], acc[nt][3]);
    }
}

// ---------------------------------------------------------------------------
// Kernel 2: reduce NSPLIT partials -> PRE-PACKED bf16 hi/lo k-pair planes.
// word[dp][n] = bf16(M[2dp][n]) | bf16(M[2dp+1][n])<<16.
// Thread -> (head h, dp 0..31, col quad c4): sums rows 2dp & 2dp+1 over 32
// partials, packs, stores uint4 to both planes.
// ---------------------------------------------------------------------------
__global__ __launch_bounds__(256) void reduce_m() {
    const int idx = blockIdx.x * 256 + threadIdx.x;
    if (idx >= HEADS * 32 * 16) return;
    const int h   = idx >> 9;            // /512
    const int rem = idx & 511;
    const int dp  = rem >> 4;
    const int c4  = (rem & 15) << 2;

    float4 s0 = make_float4(0.f, 0.f, 0.f, 0.f);
    float4 s1 = make_float4(0.f, 0.f, 0.f, 0.f);
    const float* base = g_partial + (size_t)h * NSPLIT * DIM * DIM;
    #pragma unroll
    for (int p = 0; p < NSPLIT; p++) {
        const float4 a = *(const float4*)&base[(size_t)p * DIM * DIM + (2 * dp) * DIM + c4];
        const float4 b = *(const float4*)&base[(size_t)p * DIM * DIM + (2 * dp + 1) * DIM + c4];
        s0.x += a.x; s0.y += a.y; s0.z += a.z; s0.w += a.w;
        s1.x += b.x; s1.y += b.y; s1.z += b.z; s1.w += b.w;
    }
    uint4 whi, wlo;
    pack2(s0.x, s1.x, whi.x, wlo.x);
    pack2(s0.y, s1.y, whi.y, wlo.y);
    pack2(s0.z, s1.z, whi.z, wlo.z);
    pack2(s0.w, s1.w, whi.w, wlo.w);
    *(uint4*)&g_Mhi[((size_t)h * 32 + dp) * DIM + c4] = whi;
    *(uint4*)&g_Mlo[((size_t)h * 32 + dp) * DIM + c4] = wlo;
}

// ---------------------------------------------------------------------------
// Kernel 3: out = Q @ M.  Block = 128 q-rows x 64 cols, 256 thr (8 warps).
// Qhi/Qlo[q][dp] stride 36 (banks 4g+t distinct); Mhi/Mlo[dp][n] stride 72
// copied straight from pre-packed gmem planes (no pack ALU).
// Warps: (wid&3) -> 32-row group (mt=2 of 16); (wid>>2) -> 32-col group (nt=4).
// Dynamic smem: 2*128*36*4 + 2*32*72*4 = 36.9 + 18.4 = 55.3 KB.
// ---------------------------------------------------------------------------
#define QSTR 36
#define QROWS 128
#define QM_SMEM ((2 * QROWS * QSTR + 2 * 32 * KSTR) * 4)
__global__ __launch_bounds__(256) void qm_gemm(const float* __restrict__ Qp,
                                               float* __restrict__ Op) {
    extern __shared__ __align__(16) unsigned qsm[];
    unsigned (*Qhi)[QSTR] = (unsigned (*)[QSTR])qsm;
    unsigned (*Qlo)[QSTR] = (unsigned (*)[QSTR])(qsm + QROWS * QSTR);
    unsigned (*Mhi)[KSTR] = (unsigned (*)[KSTR])(qsm + 2 * QROWS * QSTR);
    unsigned (*Mlo)[KSTR] = (unsigned (*)[KSTR])(qsm + 2 * QROWS * QSTR + 32 * KSTR);

    const int h  = blockIdx.x >> 5;            // 32 blocks per head
    const int r0 = (blockIdx.x & 31) * QROWS;

    const int tid  = threadIdx.x;
    const int wid  = tid >> 5;
    const int lane = tid & 31;
    const int g = lane >> 2;
    const int t = lane & 3;
    const int rw = (wid & 3) * 32;     // q-row group of 32
    const int c0 = (wid >> 2) * 32;    // out col group of 32

    const float* Qh = Qp + ((size_t)h * SEQ + r0) * DIM;
    const unsigned* MhiG = g_Mhi + (size_t)h * 32 * DIM;
    const unsigned* MloG = g_Mlo + (size_t)h * 32 * DIM;

    // stage M planes: plain copies (512 uint4 each)
    #pragma unroll
    for (int s = tid; s < 32 * 16; s += 256) {
        const int dp = s >> 4;
        const int c4 = (s & 15) << 2;
        *(uint4*)&Mhi[dp][c4] = *(const uint4*)&MhiG[dp * DIM + c4];
        *(uint4*)&Mlo[dp][c4] = *(const uint4*)&MloG[dp * DIM + c4];
    }
    // stage + pack Q: 128 rows x 32 dp words (1024 slots of 4 words)
    #pragma unroll
    for (int s = tid; s < QROWS * 8; s += 256) {
        const int r   = s >> 3;
        const int dp4 = (s & 7) << 2;
        const float4 qa = *(const float4*)&Qh[(size_t)r * DIM + 2 * dp4];
        const float4 qb = *(const float4*)&Qh[(size_t)r * DIM + 2 * dp4 + 4];
        uint4 whi, wlo;
        pack2(qa.x, qa.y, whi.x, wlo.x);
        pack2(qa.z, qa.w, whi.y, wlo.y);
        pack2(qb.x, qb.y, whi.z, wlo.z);
        pack2(qb.z, qb.w, whi.w, wlo.w);
        *(uint4*)&Qhi[r][dp4] = whi;
        *(uint4*)&Qlo[r][dp4] = wlo;
    }
    __syncthreads();

    float acc[2][4][4] = {};

    #pragma unroll
    for (int ks = 0; ks < 4; ks++) {            // four k16 slabs (d = 64)
        const int db = ks * 8;
        unsigned ah[2][4], al[2][4];
        #pragma unroll
        for (int mt = 0; mt < 2; mt++) {
            const int row = rw + mt * 16;
            ah[mt][0] = Qhi[row + g][db + t];         al[mt][0] = Qlo[row + g][db + t];
            ah[mt][1] = Qhi[row + g + 8][db + t];     al[mt][1] = Qlo[row + g + 8][db + t];
            ah[mt][2] = Qhi[row + g][db + t + 4];     al[mt][2] = Qlo[row + g][db + t + 4];
            ah[mt][3] = Qhi[row + g + 8][db + t + 4]; al[mt][3] = Qlo[row + g + 8][db + t + 4];
        }
        #pragma unroll
        for (int nt = 0; nt < 4; nt++) {
            const int col = c0 + nt * 8 + g;
            unsigned bh[2], bl[2];
            bh[0] = Mhi[db + t][col];     bl[0] = Mlo[db + t][col];
            bh[1] = Mhi[db + t + 4][col]; bl[1] = Mlo[db + t + 4][col];
            #pragma unroll
            for (int mt = 0; mt < 2; mt++)
                mma_x3(acc[mt][nt], ah[mt], al[mt], bh, bl);
        }
    }

    float* Oh = Op + ((size_t)h * SEQ + r0) * DIM;
    #pragma unroll
    for (int mt = 0; mt < 2; mt++) {
        #pragma unroll
        for (int nt = 0; nt < 4; nt++) {
            const int col = c0 + nt * 8 + 2 * t;
            const int row = rw + mt * 16 + g;
            *(float2*)&Oh[(size_t)row * DIM + col]       = make_float2(acc[mt][nt][0], acc[mt][nt][1]);
            *(float2*)&Oh[(size_t)(row + 8) * DIM + col] = make_float2(acc[mt][nt][2], acc[mt][nt][3]);
        }
    }
}

// ---------------------------------------------------------------------------
extern "C" void kernel_launch(void* const* d_in, const int* in_sizes, int n_in,
                              void* d_out, int out_size) {
    const float* q = (const float*)d_in[0];
    const float* k = (const float*)d_in[1];
    const float* v = (const float*)d_in[2];
    float* out = (float*)d_out;

    static int attr_done = 0;   // idempotent attribute set (not a work guard)
    if (!attr_done) {
        cudaFuncSetAttribute(qm_gemm, cudaFuncAttributeMaxDynamicSharedMemorySize, QM_SMEM);
        attr_done = 1;
    }

    ktv_partial<<<HEADS * NSPLIT, KTV_THREADS, KTV_SMEM>>>(k, v);
    reduce_m<<<(HEADS * 32 * 16 + 255) / 256, 256>>>();
    qm_gemm<<<HEADS * (SEQ / QROWS), 256, QM_SMEM>>>(q, out);
}